// round 8
// baseline (speedup 1.0000x reference)
#include <cuda_runtime.h>
#include <cstdint>

#define Bq 16
#define Nq 2048
#define Cq 3
#define Kq 100
#define THREADS 1024
#define PER (Nq / THREADS)   // 2 contiguous sorted positions per thread
#define NWORD (Nq / 64)      // 32 bitmap words
#define NROUND (Nq / 128)    // 16 rounds; round t = words {2t, 2t+1}
#define KCAP 112
#define NEGV (-1e9f)

typedef unsigned long long u64;

__device__ __forceinline__ unsigned fkey_desc(float f) {
    unsigned u = __float_as_uint(f);
    u = (u & 0x80000000u) ? ~u : (u | 0x80000000u);
    return ~u;
}
__device__ __forceinline__ float key_to_score(unsigned k) {
    unsigned u = ~k;
    u = (u & 0x80000000u) ? (u & 0x7fffffffu) : ~u;
    return __uint_as_float(u);
}

__global__ void __launch_bounds__(THREADS)
roiheads_kernel(const float* __restrict__ logit,   // [B,N,3]
                const float* __restrict__ reg,     // [B,N,6]
                const float* __restrict__ prop,    // [B,N,2]
                const int*   __restrict__ ishape,  // scalar
                float*       __restrict__ out)     // [B,2,K,3]
{
    __shared__ u64    keys[Nq];
    __shared__ float2 lohi[Nq];
    __shared__ float  keptLo[KCAP], keptHi[KCAP];
    __shared__ u64    alive[NWORD];
    __shared__ int    sDLo[2], sDHi[2];
    __shared__ int    sStop, sStopW;     // sStopW: last valid alive WORD index
    __shared__ int    wp[NWORD + 1];

    const int b      = blockIdx.x >> 1;
    const int c      = blockIdx.x & 1;
    const int cls    = c + 1;
    const int tid    = threadIdx.x;
    const int lane   = tid & 31;
    const int wid    = tid >> 5;         // warp id == owned alive word
    const int base   = tid * PER;

    int ib = ishape[0];
    float img = (ib > 0 && ib < (1 << 24)) ? (float)ib : __int_as_float(ib);

    if (tid < NWORD) alive[tid] = 0ull;
    if (tid == 0) { sDLo[0] = 0; sDHi[0] = 0; sStop = 0; sStopW = NWORD - 1; }

    // ---------- Phase 1: softmax + decode + clip + mask -> keys in regs ----------
    u64 v[PER];
    {
        const float2* lgv = (const float2*)(logit + ((size_t)b * Nq + base) * Cq);
        float2 G0 = lgv[0], G1 = lgv[1], G2 = lgv[2];
        const float4  P   = *(const float4*)(prop + ((size_t)b * Nq + base) * 2);
        float lg[6] = {G0.x, G0.y, G1.x, G1.y, G2.x, G2.y};
        float pr[4] = {P.x, P.y, P.z, P.w};

        #pragma unroll
        for (int r = 0; r < PER; r++) {
            int j = base + r;
            float l0 = lg[r*3+0], l1 = lg[r*3+1], l2 = lg[r*3+2];
            float m  = fmaxf(l0, fmaxf(l1, l2));
            float e0 = expf(l0 - m), e1 = expf(l1 - m), e2 = expf(l2 - m);
            float s  = ((cls == 1) ? e1 : e2) / (e0 + e1 + e2);

            const float2 dd = *(const float2*)(reg + ((size_t)b * Nq + j) * (2 * Cq) + 2 * cls);
            float dx = dd.x;
            float dw = fminf(dd.y, 4.0f);

            float p0 = pr[r*2+0], p1 = pr[r*2+1];
            float w   = p1 - p0;
            float ctr = p0 + 0.5f * w;
            float pc  = dx * w + ctr;
            float pw  = expf(dw) * w;
            float lo  = fminf(fmaxf(pc - 0.5f * pw, 0.0f), img);
            float hi  = fminf(fmaxf(pc + 0.5f * pw, 0.0f), img);

            bool  valid = ((hi - lo) >= 10.0f) && (s >= 0.05f);
            float ms    = valid ? s : NEGV;

            lohi[j] = make_float2(lo, hi);
            v[r] = ((u64)fkey_desc(ms) << 32) | (unsigned)j;
        }
    }

    // ---------- Phase 2: bitonic sort; smem only for strides >= 64 ----------
    for (int k = 2; k <= Nq; k <<= 1) {
        int j2 = k >> 1;
        if (j2 >= 64) {
            #pragma unroll
            for (int r = 0; r < PER; r++) keys[base + r] = v[r];
            __syncthreads();
            for (; j2 >= 64; j2 >>= 1) {
                #pragma unroll
                for (int rr = 0; rr < PER; rr++) {
                    int i  = tid + rr * THREADS;
                    int ix = i ^ j2;
                    if (ix > i) {
                        bool up = ((i & k) == 0);
                        u64 a = keys[i], bb = keys[ix];
                        if ((a > bb) == up) { keys[i] = bb; keys[ix] = a; }
                    }
                }
                __syncthreads();
            }
            #pragma unroll
            for (int r = 0; r < PER; r++) v[r] = keys[base + r];
        }
        for (; j2 >= 2; j2 >>= 1) {
            int ld = j2 >> 1;
            #pragma unroll
            for (int r = 0; r < PER; r++) {
                u64 other = __shfl_xor_sync(0xffffffffu, v[r], ld);
                int i = base + r;
                bool up    = ((i & k)  == 0);
                bool lower = ((i & j2) == 0);
                bool tmin  = (up == lower);
                u64 mn = (v[r] < other) ? v[r] : other;
                u64 mx = (v[r] < other) ? other : v[r];
                v[r] = tmin ? mn : mx;
            }
        }
        {
            bool up = ((base & k) == 0);
            u64 a = v[0], bb = v[1];
            if ((a > bb) == up) { v[0] = bb; v[1] = a; }
        }
    }

    // ---------- Phase 3: spill keys; cache owned boxes; alive bitmap ----------
    float myLo[PER], myHi[PER];
    unsigned myAlive = 0;
    #pragma unroll
    for (int r = 0; r < PER; r++) {
        keys[base + r] = v[r];
        int idx = (int)(v[r] & 0xffffffffu);
        float2 lh = lohi[idx];
        myLo[r] = lh.x;
        myHi[r] = lh.y;
        if (key_to_score((unsigned)(v[r] >> 32)) > 0.5f * NEGV)
            myAlive |= (1u << r);
    }
    if (myAlive)
        atomicOr(&alive[wid], (u64)myAlive << (lane * PER));
    __syncthreads();

    // ---------- Phase 4: pipelined NMS, 128-box rounds (1 barrier each) ----------
    // warp0 holds the current round's 128 boxes: 4 per lane
    float glo0=0.f, ghi0=0.f, glo1=0.f, ghi1=0.f;
    float glo2=0.f, ghi2=0.f, glo3=0.f, ghi3=0.f;
    int kt = 0;
    if (wid == 0) {
        float2 a0 = lohi[(int)(keys[lane      ] & 0xffffffffu)];
        float2 a1 = lohi[(int)(keys[lane + 32 ] & 0xffffffffu)];
        float2 a2 = lohi[(int)(keys[lane + 64 ] & 0xffffffffu)];
        float2 a3 = lohi[(int)(keys[lane + 96 ] & 0xffffffffu)];
        glo0=a0.x; ghi0=a0.y; glo1=a1.x; ghi1=a1.y;
        glo2=a2.x; ghi2=a2.y; glo3=a3.x; ghi3=a3.y;
    }

    for (int t = 0; t < NROUND; t++) {
        if (wid == 0) {
            u64 at0 = alive[2*t];
            u64 at1 = alive[2*t + 1];
            const float w0 = ghi0-glo0, w1 = ghi1-glo1, w2 = ghi2-glo2, w3 = ghi3-glo3;

            // urgent: apply previous round's kept delta to this round's boxes
            const int dLo = sDLo[t & 1], dHi = sDHi[t & 1];
            if ((at0 | at1) && dHi > dLo) {
                bool q0=false, q1=false, q2=false, q3=false;
                for (int s = dLo; s < dHi; s++) {
                    float pl = keptLo[s], ph = keptHi[s];
                    float pw = ph - pl;
                    float i0 = fminf(ph, ghi0) - fmaxf(pl, glo0);
                    if (i0 > 0.0f) q0 |= (i0 / fmaxf(pw + w0 - i0, 1e-8f) > 0.5f);
                    float i1 = fminf(ph, ghi1) - fmaxf(pl, glo1);
                    if (i1 > 0.0f) q1 |= (i1 / fmaxf(pw + w1 - i1, 1e-8f) > 0.5f);
                    float i2 = fminf(ph, ghi2) - fmaxf(pl, glo2);
                    if (i2 > 0.0f) q2 |= (i2 / fmaxf(pw + w2 - i2, 1e-8f) > 0.5f);
                    float i3 = fminf(ph, ghi3) - fmaxf(pl, glo3);
                    if (i3 > 0.0f) q3 |= (i3 / fmaxf(pw + w3 - i3, 1e-8f) > 0.5f);
                }
                unsigned b0 = __ballot_sync(0xffffffffu, q0);
                unsigned b1 = __ballot_sync(0xffffffffu, q1);
                unsigned b2 = __ballot_sync(0xffffffffu, q2);
                unsigned b3 = __ballot_sync(0xffffffffu, q3);
                at0 &= ~(((u64)b1 << 32) | (u64)b0);
                at1 &= ~(((u64)b3 << 32) | (u64)b2);
            }

            // greedy over the 128-box round, capped at Kq kept total
            const int T0 = kt;
            u64 kept0 = 0, kept1 = 0;
            while ((at0 | at1) && kt < Kq) {
                int pos = at0 ? (__ffsll((long long)at0) - 1)
                              : (64 + __ffsll((long long)at1) - 1);
                if (pos < 64) kept0 |= (1ull << pos); else kept1 |= (1ull << (pos - 64));

                int sel = pos >> 5;
                float candL = (sel == 0) ? glo0 : (sel == 1) ? glo1 : (sel == 2) ? glo2 : glo3;
                float candH = (sel == 0) ? ghi0 : (sel == 1) ? ghi1 : (sel == 2) ? ghi2 : ghi3;
                u64 packed = ((u64)__float_as_uint(candH) << 32) | __float_as_uint(candL);
                u64 got = __shfl_sync(0xffffffffu, packed, pos & 31);
                float pl = __uint_as_float((unsigned)(got & 0xffffffffu));
                float ph = __uint_as_float((unsigned)(got >> 32));
                float pw = ph - pl;

                bool q0=false, q1=false, q2=false, q3=false;
                float i0 = fminf(ph, ghi0) - fmaxf(pl, glo0);
                if (i0 > 0.0f) q0 = (i0 / fmaxf(pw + w0 - i0, 1e-8f) > 0.5f);
                float i1 = fminf(ph, ghi1) - fmaxf(pl, glo1);
                if (i1 > 0.0f) q1 = (i1 / fmaxf(pw + w1 - i1, 1e-8f) > 0.5f);
                float i2 = fminf(ph, ghi2) - fmaxf(pl, glo2);
                if (i2 > 0.0f) q2 = (i2 / fmaxf(pw + w2 - i2, 1e-8f) > 0.5f);
                float i3 = fminf(ph, ghi3) - fmaxf(pl, glo3);
                if (i3 > 0.0f) q3 = (i3 / fmaxf(pw + w3 - i3, 1e-8f) > 0.5f);

                unsigned b0 = __ballot_sync(0xffffffffu, q0);
                unsigned b1 = __ballot_sync(0xffffffffu, q1);
                unsigned b2 = __ballot_sync(0xffffffffu, q2);
                unsigned b3 = __ballot_sync(0xffffffffu, q3);
                at0 &= ~(((u64)b1 << 32) | (u64)b0);
                at1 &= ~(((u64)b3 << 32) | (u64)b2);
                if (pos < 64) {
                    at0 = (pos < 63) ? (at0 & (~0ull << (pos + 1))) : 0ull;
                } else {
                    at0 = 0ull;
                    int p2 = pos - 64;
                    at1 = (p2 < 63) ? (at1 & (~0ull << (p2 + 1))) : 0ull;
                }
                if (lane == 0) { keptLo[kt] = pl; keptHi[kt] = ph; }
                kt++;
            }
            if (lane == 0) {
                alive[2*t]     = kept0;
                alive[2*t + 1] = kept1;
                sDLo[(t + 1) & 1] = T0;
                sDHi[(t + 1) & 1] = kt;
                if (kt >= Kq) { sStop = 1; sStopW = 2*t + 1; }
            }
            // prefetch next round's 128 boxes
            if (t + 1 < NROUND) {
                int nb = (t + 1) * 128;
                float2 a0 = lohi[(int)(keys[nb + lane      ] & 0xffffffffu)];
                float2 a1 = lohi[(int)(keys[nb + lane + 32 ] & 0xffffffffu)];
                float2 a2 = lohi[(int)(keys[nb + lane + 64 ] & 0xffffffffu)];
                float2 a3 = lohi[(int)(keys[nb + lane + 96 ] & 0xffffffffu)];
                glo0=a0.x; ghi0=a0.y; glo1=a1.x; ghi1=a1.y;
                glo2=a2.x; ghi2=a2.y; glo3=a3.x; ghi3=a3.y;
            }
        } else {
            // background: apply previous delta to strictly-later rounds' boxes
            const int dLo = sDLo[t & 1], dHi = sDHi[t & 1];
            if (((wid >> 1) > t) && myAlive && dHi > dLo) {
                unsigned killed = 0;
                #pragma unroll
                for (int r = 0; r < PER; r++) {
                    if (myAlive & (1u << r)) {
                        float lo = myLo[r], hi = myHi[r];
                        float wb = hi - lo;
                        for (int s = dLo; s < dHi; s++) {
                            float pl = keptLo[s], ph = keptHi[s];
                            float inter = fminf(ph, hi) - fmaxf(pl, lo);
                            if (inter > 0.0f) {
                                float uni = (ph - pl) + wb - inter;
                                if (inter / fmaxf(uni, 1e-8f) > 0.5f) { killed |= (1u << r); break; }
                            }
                        }
                    }
                }
                if (killed) {
                    myAlive &= ~killed;
                    atomicAnd(&alive[wid], ~((u64)killed << (lane * PER)));
                }
            }
        }
        __syncthreads();
        if (sStop) break;   // exactly K kept found; later rounds cannot matter
    }

    if (tid < NWORD && tid > sStopW) alive[tid] = 0ull;
    __syncthreads();

    // ---------- Phase 5: ranks + emit top-K with NEG padding ----------
    if (tid == 0) {
        int acc = 0;
        #pragma unroll
        for (int w = 0; w < NWORD; w++) { wp[w] = acc; acc += __popcll(alive[w]); }
        wp[NWORD] = acc;
    }
    __syncthreads();
    const int T = wp[NWORD];
    float* o = out + ((size_t)(b * 2 + c)) * Kq * 3;

    const u64 aw = alive[wid];
    #pragma unroll
    for (int r = 0; r < PER; r++) {
        int p = base + r;
        int bit = p & 63;
        u64 lowmask = (bit == 0) ? 0ull : ((1ull << bit) - 1ull);
        int  kr   = wp[p >> 6] + __popcll(aw & lowmask);
        bool kept = (aw >> bit) & 1ull;
        if (kept) {
            if (kr < Kq) {
                o[kr * 3 + 0] = myLo[r];
                o[kr * 3 + 1] = myHi[r];
                o[kr * 3 + 2] = key_to_score((unsigned)(v[r] >> 32));
            }
        } else {
            int nr = p - kr;
            if (T < Kq && nr < Kq - T) {
                int slot = T + nr;
                o[slot * 3 + 0] = myLo[r];
                o[slot * 3 + 1] = myHi[r];
                o[slot * 3 + 2] = NEGV;
            }
        }
    }
}

extern "C" void kernel_launch(void* const* d_in, const int* in_sizes, int n_in,
                              void* d_out, int out_size)
{
    const float* logit  = (const float*)d_in[0];   // [16,2048,3]
    const float* reg    = (const float*)d_in[1];   // [16,2048,6]
    const float* prop   = (const float*)d_in[2];   // [16,2048,2]
    const int*   ishape = (const int*)d_in[3];     // scalar
    float* out = (float*)d_out;                    // [16,2,100,3]

    roiheads_kernel<<<Bq * (Cq - 1), THREADS>>>(logit, reg, prop, ishape, out);
}

// round 9
// speedup vs baseline: 1.2081x; 1.2081x over previous
#include <cuda_runtime.h>
#include <cstdint>

#define Bq 16
#define Nq 2048
#define Cq 3
#define Kq 100
#define THREADS 1024
#define PER (Nq / THREADS)   // 2 contiguous sorted positions per thread
#define NWORD (Nq / 64)      // 32 bitmap words
#define NTILE (Nq / 64)      // 32 tiles; warp w owns tile w
#define KCAP 112
#define NEGV (-1e9f)

typedef unsigned long long u64;

__device__ __forceinline__ unsigned fkey_desc(float f) {
    unsigned u = __float_as_uint(f);
    u = (u & 0x80000000u) ? ~u : (u | 0x80000000u);
    return ~u;
}
__device__ __forceinline__ float key_to_score(unsigned k) {
    unsigned u = ~k;
    u = (u & 0x80000000u) ? (u & 0x7fffffffu) : ~u;
    return __uint_as_float(u);
}

// Exactly equivalent to: (inter / fmaxf(uni, 1e-8f)) > 0.5f  for the pairs that
// matter (alive boxes have width >= 10 so uni >= 10). Decides without division
// outside a +-2e-6 relative band (division rounding is <= 0.5 ulp ~ 6e-8);
// inside the band falls back to the literal reference expression.
__device__ __forceinline__ bool iou_gt_half(float inter, float uni) {
    float h = 0.5f * uni;
    if (inter > h * 1.000002f) return true;
    if (inter < h * 0.999998f) return false;
    return inter / fmaxf(uni, 1e-8f) > 0.5f;
}

__global__ void __launch_bounds__(THREADS)
roiheads_kernel(const float* __restrict__ logit,   // [B,N,3]
                const float* __restrict__ reg,     // [B,N,6]
                const float* __restrict__ prop,    // [B,N,2]
                const int*   __restrict__ ishape,  // scalar
                float*       __restrict__ out)     // [B,2,K,3]
{
    __shared__ u64    keys[Nq];
    __shared__ float2 lohi[Nq];
    __shared__ float  keptLo[KCAP], keptHi[KCAP];
    __shared__ u64    alive[NWORD];
    __shared__ int    sDLo[2], sDHi[2];
    __shared__ int    sStop, sStopT;
    __shared__ int    wp[NWORD + 1];

    const int b      = blockIdx.x >> 1;
    const int c      = blockIdx.x & 1;
    const int cls    = c + 1;
    const int tid    = threadIdx.x;
    const int lane   = tid & 31;
    const int wid    = tid >> 5;         // warp id == owned tile
    const int base   = tid * PER;

    int ib = ishape[0];
    float img = (ib > 0 && ib < (1 << 24)) ? (float)ib : __int_as_float(ib);

    if (tid < NWORD) alive[tid] = 0ull;
    if (tid == 0) { sDLo[0] = 0; sDHi[0] = 0; sStop = 0; sStopT = NTILE - 1; }

    // ---------- Phase 1: softmax + decode + clip + mask -> keys in regs ----------
    u64 v[PER];
    {
        const float2* lgv = (const float2*)(logit + ((size_t)b * Nq + base) * Cq);
        float2 G0 = lgv[0], G1 = lgv[1], G2 = lgv[2];
        const float4  P   = *(const float4*)(prop + ((size_t)b * Nq + base) * 2);
        float lg[6] = {G0.x, G0.y, G1.x, G1.y, G2.x, G2.y};
        float pr[4] = {P.x, P.y, P.z, P.w};

        #pragma unroll
        for (int r = 0; r < PER; r++) {
            int j = base + r;
            float l0 = lg[r*3+0], l1 = lg[r*3+1], l2 = lg[r*3+2];
            float m  = fmaxf(l0, fmaxf(l1, l2));
            float e0 = expf(l0 - m), e1 = expf(l1 - m), e2 = expf(l2 - m);
            float s  = ((cls == 1) ? e1 : e2) / (e0 + e1 + e2);

            const float2 dd = *(const float2*)(reg + ((size_t)b * Nq + j) * (2 * Cq) + 2 * cls);
            float dx = dd.x;
            float dw = fminf(dd.y, 4.0f);

            float p0 = pr[r*2+0], p1 = pr[r*2+1];
            float w   = p1 - p0;
            float ctr = p0 + 0.5f * w;
            float pc  = dx * w + ctr;
            float pw  = expf(dw) * w;
            float lo  = fminf(fmaxf(pc - 0.5f * pw, 0.0f), img);
            float hi  = fminf(fmaxf(pc + 0.5f * pw, 0.0f), img);

            bool  valid = ((hi - lo) >= 10.0f) && (s >= 0.05f);
            float ms    = valid ? s : NEGV;

            lohi[j] = make_float2(lo, hi);
            v[r] = ((u64)fkey_desc(ms) << 32) | (unsigned)j;
        }
    }

    // ---------- Phase 2: bitonic sort; smem only for strides >= 64 ----------
    for (int k = 2; k <= Nq; k <<= 1) {
        int j2 = k >> 1;
        if (j2 >= 64) {
            #pragma unroll
            for (int r = 0; r < PER; r++) keys[base + r] = v[r];
            __syncthreads();
            for (; j2 >= 64; j2 >>= 1) {
                #pragma unroll
                for (int rr = 0; rr < PER; rr++) {
                    int i  = tid + rr * THREADS;
                    int ix = i ^ j2;
                    if (ix > i) {
                        bool up = ((i & k) == 0);
                        u64 a = keys[i], bb = keys[ix];
                        if ((a > bb) == up) { keys[i] = bb; keys[ix] = a; }
                    }
                }
                __syncthreads();
            }
            #pragma unroll
            for (int r = 0; r < PER; r++) v[r] = keys[base + r];
        }
        for (; j2 >= 2; j2 >>= 1) {
            int ld = j2 >> 1;
            #pragma unroll
            for (int r = 0; r < PER; r++) {
                u64 other = __shfl_xor_sync(0xffffffffu, v[r], ld);
                int i = base + r;
                bool up    = ((i & k)  == 0);
                bool lower = ((i & j2) == 0);
                bool tmin  = (up == lower);
                u64 mn = (v[r] < other) ? v[r] : other;
                u64 mx = (v[r] < other) ? other : v[r];
                v[r] = tmin ? mn : mx;
            }
        }
        {
            bool up = ((base & k) == 0);
            u64 a = v[0], bb = v[1];
            if ((a > bb) == up) { v[0] = bb; v[1] = a; }
        }
    }

    // ---------- Phase 3: spill keys; cache owned boxes; alive bitmap ----------
    float myLo[PER], myHi[PER];
    unsigned myAlive = 0;
    #pragma unroll
    for (int r = 0; r < PER; r++) {
        keys[base + r] = v[r];
        int idx = (int)(v[r] & 0xffffffffu);
        float2 lh = lohi[idx];
        myLo[r] = lh.x;
        myHi[r] = lh.y;
        if (key_to_score((unsigned)(v[r] >> 32)) > 0.5f * NEGV)
            myAlive |= (1u << r);
    }
    if (myAlive)
        atomicOr(&alive[wid], (u64)myAlive << (lane * PER));
    __syncthreads();

    // ---------- Phase 4: pipelined tile NMS (1 barrier / tile) ----------
    float glo0 = 0.f, ghi0 = 0.f, glo1 = 0.f, ghi1 = 0.f;
    int kt = 0;
    if (wid == 0) {
        float2 a0 = lohi[(int)(keys[lane     ] & 0xffffffffu)];
        float2 a1 = lohi[(int)(keys[lane + 32] & 0xffffffffu)];
        glo0 = a0.x; ghi0 = a0.y; glo1 = a1.x; ghi1 = a1.y;
    }

    for (int t = 0; t < NTILE; t++) {
        if (wid == 0) {
            u64 at = alive[t];
            const float w0 = ghi0 - glo0, w1 = ghi1 - glo1;
            // urgent: apply previous tile's kept delta to this tile's boxes
            const int dLo = sDLo[t & 1], dHi = sDHi[t & 1];
            if (at != 0ull && dHi > dLo) {
                bool q0 = false, q1 = false;
                for (int s = dLo; s < dHi; s++) {
                    float pl = keptLo[s], ph = keptHi[s];
                    float pw = ph - pl;
                    float i0 = fminf(ph, ghi0) - fmaxf(pl, glo0);
                    if (i0 > 0.0f) q0 |= iou_gt_half(i0, pw + w0 - i0);
                    float i1 = fminf(ph, ghi1) - fmaxf(pl, glo1);
                    if (i1 > 0.0f) q1 |= iou_gt_half(i1, pw + w1 - i1);
                }
                unsigned b0 = __ballot_sync(0xffffffffu, q0);
                unsigned b1 = __ballot_sync(0xffffffffu, q1);
                at &= ~(((u64)b1 << 32) | (u64)b0);
            }
            // greedy over the tile, capped at Kq kept total
            const int T0 = kt;
            u64 kept = 0;
            while (at && kt < Kq) {
                int pos = __ffsll((long long)at) - 1;
                kept |= (1ull << pos);
                float candL = (pos & 32) ? glo1 : glo0;
                float candH = (pos & 32) ? ghi1 : ghi0;
                u64 packed = ((u64)__float_as_uint(candH) << 32) | __float_as_uint(candL);
                u64 got = __shfl_sync(0xffffffffu, packed, pos & 31);
                float pl = __uint_as_float((unsigned)(got & 0xffffffffu));
                float ph = __uint_as_float((unsigned)(got >> 32));
                float pw = ph - pl;
                bool q0 = false, q1 = false;
                {
                    float inter = fminf(ph, ghi0) - fmaxf(pl, glo0);
                    if (inter > 0.0f) q0 = iou_gt_half(inter, pw + w0 - inter);
                    inter = fminf(ph, ghi1) - fmaxf(pl, glo1);
                    if (inter > 0.0f) q1 = iou_gt_half(inter, pw + w1 - inter);
                }
                unsigned b0 = __ballot_sync(0xffffffffu, q0);
                unsigned b1 = __ballot_sync(0xffffffffu, q1);
                at &= ~(((u64)b1 << 32) | (u64)b0);
                at = (pos < 63) ? (at & (~0ull << (pos + 1))) : 0ull;
                if (lane == 0) { keptLo[kt] = pl; keptHi[kt] = ph; }
                kt++;
            }
            if (lane == 0) {
                alive[t] = kept;
                sDLo[(t + 1) & 1] = T0;
                sDHi[(t + 1) & 1] = kt;
                if (kt >= Kq) { sStop = 1; sStopT = t; }
            }
            // prefetch next tile's boxes
            if (t + 1 < NTILE) {
                float2 a0 = lohi[(int)(keys[(t + 1) * 64 + lane     ] & 0xffffffffu)];
                float2 a1 = lohi[(int)(keys[(t + 1) * 64 + lane + 32] & 0xffffffffu)];
                glo0 = a0.x; ghi0 = a0.y; glo1 = a1.x; ghi1 = a1.y;
            }
        } else {
            // background: apply previous delta to strictly-later owned tiles
            const int dLo = sDLo[t & 1], dHi = sDHi[t & 1];
            if (wid > t && myAlive && dHi > dLo) {
                unsigned killed = 0;
                #pragma unroll
                for (int r = 0; r < PER; r++) {
                    if (myAlive & (1u << r)) {
                        float lo = myLo[r], hi = myHi[r];
                        float wb = hi - lo;
                        for (int s = dLo; s < dHi; s++) {
                            float pl = keptLo[s], ph = keptHi[s];
                            float inter = fminf(ph, hi) - fmaxf(pl, lo);
                            if (inter > 0.0f &&
                                iou_gt_half(inter, (ph - pl) + wb - inter)) {
                                killed |= (1u << r);
                                break;
                            }
                        }
                    }
                }
                if (killed) {
                    myAlive &= ~killed;
                    atomicAnd(&alive[wid], ~((u64)killed << (lane * PER)));
                }
            }
        }
        __syncthreads();
        if (sStop) break;   // exactly K kept found; later tiles cannot matter
    }

    if (tid < NWORD && tid > sStopT) alive[tid] = 0ull;
    __syncthreads();

    // ---------- Phase 5: ranks + emit top-K with NEG padding ----------
    if (tid == 0) {
        int acc = 0;
        #pragma unroll
        for (int w = 0; w < NWORD; w++) { wp[w] = acc; acc += __popcll(alive[w]); }
        wp[NWORD] = acc;
    }
    __syncthreads();
    const int T = wp[NWORD];
    float* o = out + ((size_t)(b * 2 + c)) * Kq * 3;

    const u64 aw = alive[wid];
    #pragma unroll
    for (int r = 0; r < PER; r++) {
        int p = base + r;
        int bit = p & 63;
        u64 lowmask = (bit == 0) ? 0ull : ((1ull << bit) - 1ull);
        int  kr   = wp[p >> 6] + __popcll(aw & lowmask);
        bool kept = (aw >> bit) & 1ull;
        if (kept) {
            if (kr < Kq) {
                o[kr * 3 + 0] = myLo[r];
                o[kr * 3 + 1] = myHi[r];
                o[kr * 3 + 2] = key_to_score((unsigned)(v[r] >> 32));
            }
        } else {
            int nr = p - kr;
            if (T < Kq && nr < Kq - T) {
                int slot = T + nr;
                o[slot * 3 + 0] = myLo[r];
                o[slot * 3 + 1] = myHi[r];
                o[slot * 3 + 2] = NEGV;
            }
        }
    }
}

extern "C" void kernel_launch(void* const* d_in, const int* in_sizes, int n_in,
                              void* d_out, int out_size)
{
    const float* logit  = (const float*)d_in[0];   // [16,2048,3]
    const float* reg    = (const float*)d_in[1];   // [16,2048,6]
    const float* prop   = (const float*)d_in[2];   // [16,2048,2]
    const int*   ishape = (const int*)d_in[3];     // scalar
    float* out = (float*)d_out;                    // [16,2,100,3]

    roiheads_kernel<<<Bq * (Cq - 1), THREADS>>>(logit, reg, prop, ishape, out);
}

// round 10
// speedup vs baseline: 1.2964x; 1.0731x over previous
#include <cuda_runtime.h>
#include <cstdint>

#define Bq 16
#define Nq 2048
#define Cq 3
#define Kq 100
#define THREADS 1024
#define PER (Nq / THREADS)   // 2 contiguous sorted positions per thread
#define NWORD (Nq / 64)      // 32 bitmap words
#define NTILE (Nq / 64)      // 32 tiles; warp w owns tile w
#define KCAP 112
#define NEGV (-1e9f)

typedef unsigned long long u64;

__device__ __forceinline__ unsigned fkey_desc(float f) {
    unsigned u = __float_as_uint(f);
    u = (u & 0x80000000u) ? ~u : (u | 0x80000000u);
    return ~u;
}
__device__ __forceinline__ float key_to_score(unsigned k) {
    unsigned u = ~k;
    u = (u & 0x80000000u) ? (u & 0x7fffffffu) : ~u;
    return __uint_as_float(u);
}

// Exactly equivalent to (inter / fmaxf(uni,1e-8f)) > 0.5f for pairs that matter
// (alive boxes have width >= 10 so uni >= 10). Band fallback uses the literal
// reference expression; division rounding (<=0.5ulp) can't cross the band.
__device__ __forceinline__ bool iou_gt_half(float inter, float uni) {
    float h = 0.5f * uni;
    if (inter > h * 1.000002f) return true;
    if (inter < h * 0.999998f) return false;
    return inter / fmaxf(uni, 1e-8f) > 0.5f;
}

__global__ void __launch_bounds__(THREADS)
roiheads_kernel(const float* __restrict__ logit,   // [B,N,3]
                const float* __restrict__ reg,     // [B,N,6]
                const float* __restrict__ prop,    // [B,N,2]
                const int*   __restrict__ ishape,  // scalar
                float*       __restrict__ out)     // [B,2,K,3]
{
    __shared__ u64    keys[Nq];
    __shared__ float2 lohi[Nq];
    __shared__ float2 keptLH[KCAP];      // interleaved (lo,hi) kept list
    __shared__ u64    alive[NWORD];
    __shared__ int    sDLo[2], sDHi[2];
    __shared__ int    sStop, sStopT;
    __shared__ int    wp[NWORD + 1];

    const int b      = blockIdx.x >> 1;
    const int c      = blockIdx.x & 1;
    const int cls    = c + 1;
    const int tid    = threadIdx.x;
    const int lane   = tid & 31;
    const int wid    = tid >> 5;         // warp id == owned tile
    const int base   = tid * PER;

    int ib = ishape[0];
    float img = (ib > 0 && ib < (1 << 24)) ? (float)ib : __int_as_float(ib);

    if (tid < NWORD) alive[tid] = 0ull;
    if (tid == 0) { sDLo[0] = 0; sDHi[0] = 0; sStop = 0; sStopT = NTILE - 1; }

    // ---------- Phase 1: softmax + decode + clip + mask -> keys in regs ----------
    u64 v[PER];
    {
        const float2* lgv = (const float2*)(logit + ((size_t)b * Nq + base) * Cq);
        float2 G0 = lgv[0], G1 = lgv[1], G2 = lgv[2];
        const float4  P   = *(const float4*)(prop + ((size_t)b * Nq + base) * 2);
        float lg[6] = {G0.x, G0.y, G1.x, G1.y, G2.x, G2.y};
        float pr[4] = {P.x, P.y, P.z, P.w};

        #pragma unroll
        for (int r = 0; r < PER; r++) {
            int j = base + r;
            float l0 = lg[r*3+0], l1 = lg[r*3+1], l2 = lg[r*3+2];
            float m  = fmaxf(l0, fmaxf(l1, l2));
            float e0 = expf(l0 - m), e1 = expf(l1 - m), e2 = expf(l2 - m);
            float s  = ((cls == 1) ? e1 : e2) / (e0 + e1 + e2);

            const float2 dd = *(const float2*)(reg + ((size_t)b * Nq + j) * (2 * Cq) + 2 * cls);
            float dx = dd.x;
            float dw = fminf(dd.y, 4.0f);

            float p0 = pr[r*2+0], p1 = pr[r*2+1];
            float w   = p1 - p0;
            float ctr = p0 + 0.5f * w;
            float pc  = dx * w + ctr;
            float pw  = expf(dw) * w;
            float lo  = fminf(fmaxf(pc - 0.5f * pw, 0.0f), img);
            float hi  = fminf(fmaxf(pc + 0.5f * pw, 0.0f), img);

            bool  valid = ((hi - lo) >= 10.0f) && (s >= 0.05f);
            float ms    = valid ? s : NEGV;

            lohi[j] = make_float2(lo, hi);
            v[r] = ((u64)fkey_desc(ms) << 32) | (unsigned)j;
        }
    }

    // ---------- Phase 2: bitonic sort; smem only for strides >= 64 ----------
    for (int k = 2; k <= Nq; k <<= 1) {
        int j2 = k >> 1;
        if (j2 >= 64) {
            #pragma unroll
            for (int r = 0; r < PER; r++) keys[base + r] = v[r];
            __syncthreads();
            for (; j2 >= 64; j2 >>= 1) {
                #pragma unroll
                for (int rr = 0; rr < PER; rr++) {
                    int i  = tid + rr * THREADS;
                    int ix = i ^ j2;
                    if (ix > i) {
                        bool up = ((i & k) == 0);
                        u64 a = keys[i], bb = keys[ix];
                        if ((a > bb) == up) { keys[i] = bb; keys[ix] = a; }
                    }
                }
                __syncthreads();
            }
            #pragma unroll
            for (int r = 0; r < PER; r++) v[r] = keys[base + r];
        }
        for (; j2 >= 2; j2 >>= 1) {
            int ld = j2 >> 1;
            #pragma unroll
            for (int r = 0; r < PER; r++) {
                u64 other = __shfl_xor_sync(0xffffffffu, v[r], ld);
                int i = base + r;
                bool up    = ((i & k)  == 0);
                bool lower = ((i & j2) == 0);
                bool tmin  = (up == lower);
                u64 mn = (v[r] < other) ? v[r] : other;
                u64 mx = (v[r] < other) ? other : v[r];
                v[r] = tmin ? mn : mx;
            }
        }
        {
            bool up = ((base & k) == 0);
            u64 a = v[0], bb = v[1];
            if ((a > bb) == up) { v[0] = bb; v[1] = a; }
        }
    }

    // ---------- Phase 3: spill keys; cache owned boxes; alive bitmap ----------
    float myLo[PER], myHi[PER];
    unsigned myAlive = 0;
    #pragma unroll
    for (int r = 0; r < PER; r++) {
        keys[base + r] = v[r];
        int idx = (int)(v[r] & 0xffffffffu);
        float2 lh = lohi[idx];
        myLo[r] = lh.x;
        myHi[r] = lh.y;
        if (key_to_score((unsigned)(v[r] >> 32)) > 0.5f * NEGV)
            myAlive |= (1u << r);
    }
    if (myAlive)
        atomicOr(&alive[wid], (u64)myAlive << (lane * PER));
    __syncthreads();

    // ---------- Phase 4: pipelined tile NMS with dead-round skipping ----------
    int kt = 0;          // warp0's kept total (uniform across warp0)
    int dLo = 0, dHi = 0;  // current round's delta bounds (uniform across block)

    for (int t = 0; t < NTILE; t++) {
        u64 at = alive[t];   // stable: last write >= 1 barrier ago (skipped rounds write nothing)
        if (at == 0ull && dHi <= dLo) {
            // dead round: nothing to greedy, nothing to suppress, no smem writes.
            // Produced delta is empty -> carry dLo/dHi unchanged. No barrier needed.
            continue;
        }

        if (wid == 0) {
            // load this tile's boxes (2 per lane)
            float2 a0 = lohi[(int)(keys[t * 64 + lane     ] & 0xffffffffu)];
            float2 a1 = lohi[(int)(keys[t * 64 + lane + 32] & 0xffffffffu)];
            float glo0 = a0.x, ghi0 = a0.y, glo1 = a1.x, ghi1 = a1.y;
            const float w0 = ghi0 - glo0, w1 = ghi1 - glo1;

            // urgent: apply previous active round's kept delta to this tile
            if (at != 0ull && dHi > dLo) {
                bool q0 = false, q1 = false;
                for (int s = dLo; s < dHi; s++) {
                    float2 p = keptLH[s];
                    float pw = p.y - p.x;
                    float i0 = fminf(p.y, ghi0) - fmaxf(p.x, glo0);
                    if (i0 > 0.0f) q0 |= iou_gt_half(i0, pw + w0 - i0);
                    float i1 = fminf(p.y, ghi1) - fmaxf(p.x, glo1);
                    if (i1 > 0.0f) q1 |= iou_gt_half(i1, pw + w1 - i1);
                }
                unsigned b0 = __ballot_sync(0xffffffffu, q0);
                unsigned b1 = __ballot_sync(0xffffffffu, q1);
                at &= ~(((u64)b1 << 32) | (u64)b0);
            }

            // greedy over the tile, capped at Kq kept total
            const int T0 = kt;
            u64 kept = 0;
            while (at && kt < Kq) {
                int pos = __ffsll((long long)at) - 1;
                kept |= (1ull << pos);
                float candL = (pos & 32) ? glo1 : glo0;
                float candH = (pos & 32) ? ghi1 : ghi0;
                u64 packed = ((u64)__float_as_uint(candH) << 32) | __float_as_uint(candL);
                u64 got = __shfl_sync(0xffffffffu, packed, pos & 31);
                float pl = __uint_as_float((unsigned)(got & 0xffffffffu));
                float ph = __uint_as_float((unsigned)(got >> 32));
                float pw = ph - pl;
                bool q0 = false, q1 = false;
                {
                    float inter = fminf(ph, ghi0) - fmaxf(pl, glo0);
                    if (inter > 0.0f) q0 = iou_gt_half(inter, pw + w0 - inter);
                    inter = fminf(ph, ghi1) - fmaxf(pl, glo1);
                    if (inter > 0.0f) q1 = iou_gt_half(inter, pw + w1 - inter);
                }
                unsigned b0 = __ballot_sync(0xffffffffu, q0);
                unsigned b1 = __ballot_sync(0xffffffffu, q1);
                at &= ~(((u64)b1 << 32) | (u64)b0);
                at = (pos < 63) ? (at & (~0ull << (pos + 1))) : 0ull;
                if (lane == 0) keptLH[kt] = make_float2(pl, ph);
                kt++;
            }
            if (lane == 0) {
                alive[t] = kept;
                sDLo[0] = T0;
                sDHi[0] = kt;
                if (kt >= Kq) { sStop = 1; sStopT = t; }
            }
        } else {
            // background: apply current delta to strictly-later owned tiles
            if (wid > t && myAlive && dHi > dLo) {
                unsigned killed = 0;
                #pragma unroll
                for (int r = 0; r < PER; r++) {
                    if (myAlive & (1u << r)) {
                        float lo = myLo[r], hi = myHi[r];
                        float wb = hi - lo;
                        for (int s = dLo; s < dHi; s++) {
                            float2 p = keptLH[s];
                            float inter = fminf(p.y, hi) - fmaxf(p.x, lo);
                            if (inter > 0.0f &&
                                iou_gt_half(inter, (p.y - p.x) + wb - inter)) {
                                killed |= (1u << r);
                                break;
                            }
                        }
                    }
                }
                if (killed) {
                    myAlive &= ~killed;
                    atomicAnd(&alive[wid], ~((u64)killed << (lane * PER)));
                }
            }
        }
        __syncthreads();
        if (sStop) break;   // exactly K kept found; later tiles cannot matter
        dLo = sDLo[0];      // delta produced by this active round (visible post-barrier)
        dHi = sDHi[0];
    }

    if (tid < NWORD && tid > sStopT) alive[tid] = 0ull;
    __syncthreads();

    // ---------- Phase 5: ranks + emit top-K with NEG padding ----------
    if (tid == 0) {
        int acc = 0;
        #pragma unroll
        for (int w = 0; w < NWORD; w++) { wp[w] = acc; acc += __popcll(alive[w]); }
        wp[NWORD] = acc;
    }
    __syncthreads();
    const int T = wp[NWORD];
    float* o = out + ((size_t)(b * 2 + c)) * Kq * 3;

    const u64 aw = alive[wid];
    #pragma unroll
    for (int r = 0; r < PER; r++) {
        int p = base + r;
        int bit = p & 63;
        u64 lowmask = (bit == 0) ? 0ull : ((1ull << bit) - 1ull);
        int  kr   = wp[p >> 6] + __popcll(aw & lowmask);
        bool kept = (aw >> bit) & 1ull;
        if (kept) {
            if (kr < Kq) {
                o[kr * 3 + 0] = myLo[r];
                o[kr * 3 + 1] = myHi[r];
                o[kr * 3 + 2] = key_to_score((unsigned)(v[r] >> 32));
            }
        } else {
            int nr = p - kr;
            if (T < Kq && nr < Kq - T) {
                int slot = T + nr;
                o[slot * 3 + 0] = myLo[r];
                o[slot * 3 + 1] = myHi[r];
                o[slot * 3 + 2] = NEGV;
            }
        }
    }
}

extern "C" void kernel_launch(void* const* d_in, const int* in_sizes, int n_in,
                              void* d_out, int out_size)
{
    const float* logit  = (const float*)d_in[0];   // [16,2048,3]
    const float* reg    = (const float*)d_in[1];   // [16,2048,6]
    const float* prop   = (const float*)d_in[2];   // [16,2048,2]
    const int*   ishape = (const int*)d_in[3];     // scalar
    float* out = (float*)d_out;                    // [16,2,100,3]

    roiheads_kernel<<<Bq * (Cq - 1), THREADS>>>(logit, reg, prop, ishape, out);
}

// round 11
// speedup vs baseline: 1.3224x; 1.0201x over previous
#include <cuda_runtime.h>
#include <cstdint>

#define Bq 16
#define Nq 2048
#define Cq 3
#define Kq 100
#define THREADS 1024
#define PER (Nq / THREADS)   // 2 sorted positions per thread (contiguous, base=2*tid)
#define NWORD (Nq / 64)      // 32 bitmap words
#define NTILE (Nq / 64)      // 32 tiles; warp w owns tile w
#define KCAP 112
#define NEGV (-1e9f)
#define HSTRIDE 66           // u16 histogram row stride (bank-conflict-free scan)

// dynamic smem layout (bytes)
#define OFF_KEYSA 0
#define OFF_KEYSB 16384
#define OFF_LOHI  32768
#define OFF_HIST  49152                       // u16[256*66] = 33792
#define OFF_DTOT  (49152 + 33792)             // u32[256]
#define OFF_DBASE (OFF_DTOT + 1024)           // u32[256]
#define SMEM_DYN  (OFF_DBASE + 1024)          // 84992

typedef unsigned long long u64;

__device__ __forceinline__ unsigned fkey_desc(float f) {
    unsigned u = __float_as_uint(f);
    u = (u & 0x80000000u) ? ~u : (u | 0x80000000u);
    return ~u;
}
__device__ __forceinline__ float key_to_score(unsigned k) {
    unsigned u = ~k;
    u = (u & 0x80000000u) ? (u & 0x7fffffffu) : ~u;
    return __uint_as_float(u);
}

// Exactly equivalent to (inter / fmaxf(uni,1e-8f)) > 0.5f for pairs that matter
// (alive boxes have width >= 10 so uni >= 10). Band fallback uses the literal
// reference expression; division rounding (<=0.5ulp) can't cross the band.
__device__ __forceinline__ bool iou_gt_half(float inter, float uni) {
    float h = 0.5f * uni;
    if (inter > h * 1.000002f) return true;
    if (inter < h * 0.999998f) return false;
    return inter / fmaxf(uni, 1e-8f) > 0.5f;
}

__global__ void __launch_bounds__(THREADS)
roiheads_kernel(const float* __restrict__ logit,   // [B,N,3]
                const float* __restrict__ reg,     // [B,N,6]
                const float* __restrict__ prop,    // [B,N,2]
                const int*   __restrict__ ishape,  // scalar
                float*       __restrict__ out)     // [B,2,K,3]
{
    extern __shared__ unsigned char dynsm[];
    u64*            keysA = (u64*)(dynsm + OFF_KEYSA);
    u64*            keysB = (u64*)(dynsm + OFF_KEYSB);
    float2*         lohi  = (float2*)(dynsm + OFF_LOHI);
    unsigned short* hist  = (unsigned short*)(dynsm + OFF_HIST);
    unsigned*       dtot  = (unsigned*)(dynsm + OFF_DTOT);
    unsigned*       dbase = (unsigned*)(dynsm + OFF_DBASE);

    __shared__ float2 keptLH[KCAP];
    __shared__ u64    alive[NWORD];
    __shared__ int    sDLo[2], sDHi[2];
    __shared__ int    sStop, sStopT;
    __shared__ int    wp[NWORD + 1];

    const int b    = blockIdx.x >> 1;
    const int c    = blockIdx.x & 1;
    const int cls  = c + 1;
    const int tid  = threadIdx.x;
    const int lane = tid & 31;
    const int wid  = tid >> 5;           // warp id == owned NMS tile
    const int base = tid * PER;

    int ib = ishape[0];
    float img = (ib > 0 && ib < (1 << 24)) ? (float)ib : __int_as_float(ib);

    if (tid < NWORD) alive[tid] = 0ull;
    if (tid == 0) { sDLo[0] = 0; sDHi[0] = 0; sStop = 0; sStopT = NTILE - 1; }

    // ---------- Phase 1: softmax + decode + clip + mask -> keysA ----------
    {
        const float2* lgv = (const float2*)(logit + ((size_t)b * Nq + base) * Cq);
        float2 G0 = lgv[0], G1 = lgv[1], G2 = lgv[2];
        const float4  P   = *(const float4*)(prop + ((size_t)b * Nq + base) * 2);
        float lg[6] = {G0.x, G0.y, G1.x, G1.y, G2.x, G2.y};
        float pr[4] = {P.x, P.y, P.z, P.w};

        #pragma unroll
        for (int r = 0; r < PER; r++) {
            int j = base + r;
            float l0 = lg[r*3+0], l1 = lg[r*3+1], l2 = lg[r*3+2];
            float m  = fmaxf(l0, fmaxf(l1, l2));
            float e0 = expf(l0 - m), e1 = expf(l1 - m), e2 = expf(l2 - m);
            float s  = ((cls == 1) ? e1 : e2) / (e0 + e1 + e2);

            const float2 dd = *(const float2*)(reg + ((size_t)b * Nq + j) * (2 * Cq) + 2 * cls);
            float dx = dd.x;
            float dw = fminf(dd.y, 4.0f);

            float p0 = pr[r*2+0], p1 = pr[r*2+1];
            float w   = p1 - p0;
            float ctr = p0 + 0.5f * w;
            float pc  = dx * w + ctr;
            float pw  = expf(dw) * w;
            float lo  = fminf(fmaxf(pc - 0.5f * pw, 0.0f), img);
            float hi  = fminf(fmaxf(pc + 0.5f * pw, 0.0f), img);

            bool  valid = ((hi - lo) >= 10.0f) && (s >= 0.05f);
            float ms    = valid ? s : NEGV;

            lohi[j]  = make_float2(lo, hi);
            keysA[j] = ((u64)fkey_desc(ms) << 32) | (unsigned)j;
        }
    }
    __syncthreads();

    // ---------- Phase 2: stable LSD radix sort on score key (4 x 8-bit) ----------
    // element rows: row = elementIndex/32; warp w handles rows w (elems tid)
    // and 32+w (elems tid+1024). Stability: rows ascend with element index;
    // within-row order = lane order; low 32 bits (idx) are the tie baseline.
    {
        u64* src = keysA;
        u64* dst = keysB;
        const unsigned lt = (1u << lane) - 1u;
        #pragma unroll
        for (int p = 0; p < 4; p++) {
            const int sh = 32 + p * 8;
            for (int i = tid; i < 256 * HSTRIDE; i += THREADS) hist[i] = 0;
            __syncthreads();

            u64 k0 = src[tid];
            u64 k1 = src[tid + 1024];
            unsigned d0 = (unsigned)(k0 >> sh) & 0xFFu;
            unsigned d1 = (unsigned)(k1 >> sh) & 0xFFu;
            unsigned m0 = __match_any_sync(0xffffffffu, d0);
            unsigned m1 = __match_any_sync(0xffffffffu, d1);
            if (__ffs(m0) - 1 == lane)
                hist[d0 * HSTRIDE + wid]      = (unsigned short)__popc(m0);
            if (__ffs(m1) - 1 == lane)
                hist[d1 * HSTRIDE + 32 + wid] = (unsigned short)__popc(m1);
            __syncthreads();

            if (tid < 256) {           // per-digit exclusive row prefix (in place)
                unsigned short* h = hist + tid * HSTRIDE;
                unsigned sum = 0;
                #pragma unroll
                for (int i = 0; i < 64; i++) {
                    unsigned t = h[i];
                    h[i] = (unsigned short)sum;
                    sum += t;
                }
                dtot[tid] = sum;
            }
            __syncthreads();

            if (tid < 32) {            // exclusive scan of 256 digit totals
                unsigned t8[8], run = 0;
                #pragma unroll
                for (int i = 0; i < 8; i++) t8[i] = dtot[tid * 8 + i];
                #pragma unroll
                for (int i = 0; i < 8; i++) { unsigned u = t8[i]; t8[i] = run; run += u; }
                unsigned inc = run;
                #pragma unroll
                for (int d = 1; d < 32; d <<= 1) {
                    unsigned x = __shfl_up_sync(0xffffffffu, inc, d);
                    if (lane >= d) inc += x;
                }
                unsigned excl = inc - run;
                #pragma unroll
                for (int i = 0; i < 8; i++) dbase[tid * 8 + i] = excl + t8[i];
            }
            __syncthreads();

            dst[dbase[d0] + hist[d0 * HSTRIDE + wid]      + __popc(m0 & lt)] = k0;
            dst[dbase[d1] + hist[d1 * HSTRIDE + 32 + wid] + __popc(m1 & lt)] = k1;
            __syncthreads();

            u64* tmp = src; src = dst; dst = tmp;   // after 4 passes: data in keysA
        }
    }

    // ---------- Phase 3: cache owned sorted boxes; alive bitmap ----------
    u64 myKey[PER];
    float myLo[PER], myHi[PER];
    unsigned myAlive = 0;
    #pragma unroll
    for (int r = 0; r < PER; r++) {
        u64 key = keysA[base + r];
        myKey[r] = key;
        float2 lh = lohi[(int)(key & 0xffffffffu)];
        myLo[r] = lh.x;
        myHi[r] = lh.y;
        if (key_to_score((unsigned)(key >> 32)) > 0.5f * NEGV)
            myAlive |= (1u << r);
    }
    if (myAlive)
        atomicOr(&alive[wid], (u64)myAlive << (lane * PER));
    __syncthreads();

    // ---------- Phase 4: pipelined tile NMS with dead-round skipping ----------
    int kt = 0;
    int dLo = 0, dHi = 0;

    for (int t = 0; t < NTILE; t++) {
        u64 at = alive[t];
        if (at == 0ull && dHi <= dLo) continue;   // dead round: no work, no writes

        if (wid == 0) {
            float2 a0 = lohi[(int)(keysA[t * 64 + lane     ] & 0xffffffffu)];
            float2 a1 = lohi[(int)(keysA[t * 64 + lane + 32] & 0xffffffffu)];
            float glo0 = a0.x, ghi0 = a0.y, glo1 = a1.x, ghi1 = a1.y;
            const float w0 = ghi0 - glo0, w1 = ghi1 - glo1;

            if (at != 0ull && dHi > dLo) {
                bool q0 = false, q1 = false;
                for (int s = dLo; s < dHi; s++) {
                    float2 p = keptLH[s];
                    float pw = p.y - p.x;
                    float i0 = fminf(p.y, ghi0) - fmaxf(p.x, glo0);
                    if (i0 > 0.0f) q0 |= iou_gt_half(i0, pw + w0 - i0);
                    float i1 = fminf(p.y, ghi1) - fmaxf(p.x, glo1);
                    if (i1 > 0.0f) q1 |= iou_gt_half(i1, pw + w1 - i1);
                }
                unsigned b0 = __ballot_sync(0xffffffffu, q0);
                unsigned b1 = __ballot_sync(0xffffffffu, q1);
                at &= ~(((u64)b1 << 32) | (u64)b0);
            }

            const int T0 = kt;
            u64 kept = 0;
            while (at && kt < Kq) {
                int pos = __ffsll((long long)at) - 1;
                kept |= (1ull << pos);
                float candL = (pos & 32) ? glo1 : glo0;
                float candH = (pos & 32) ? ghi1 : ghi0;
                u64 packed = ((u64)__float_as_uint(candH) << 32) | __float_as_uint(candL);
                u64 got = __shfl_sync(0xffffffffu, packed, pos & 31);
                float pl = __uint_as_float((unsigned)(got & 0xffffffffu));
                float ph = __uint_as_float((unsigned)(got >> 32));
                float pw = ph - pl;
                bool q0 = false, q1 = false;
                {
                    float inter = fminf(ph, ghi0) - fmaxf(pl, glo0);
                    if (inter > 0.0f) q0 = iou_gt_half(inter, pw + w0 - inter);
                    inter = fminf(ph, ghi1) - fmaxf(pl, glo1);
                    if (inter > 0.0f) q1 = iou_gt_half(inter, pw + w1 - inter);
                }
                unsigned b0 = __ballot_sync(0xffffffffu, q0);
                unsigned b1 = __ballot_sync(0xffffffffu, q1);
                at &= ~(((u64)b1 << 32) | (u64)b0);
                at = (pos < 63) ? (at & (~0ull << (pos + 1))) : 0ull;
                if (lane == 0) keptLH[kt] = make_float2(pl, ph);
                kt++;
            }
            if (lane == 0) {
                alive[t] = kept;
                sDLo[0] = T0;
                sDHi[0] = kt;
                if (kt >= Kq) { sStop = 1; sStopT = t; }
            }
        } else {
            if (wid > t && myAlive && dHi > dLo) {
                unsigned killed = 0;
                #pragma unroll
                for (int r = 0; r < PER; r++) {
                    if (myAlive & (1u << r)) {
                        float lo = myLo[r], hi = myHi[r];
                        float wb = hi - lo;
                        for (int s = dLo; s < dHi; s++) {
                            float2 p = keptLH[s];
                            float inter = fminf(p.y, hi) - fmaxf(p.x, lo);
                            if (inter > 0.0f &&
                                iou_gt_half(inter, (p.y - p.x) + wb - inter)) {
                                killed |= (1u << r);
                                break;
                            }
                        }
                    }
                }
                if (killed) {
                    myAlive &= ~killed;
                    atomicAnd(&alive[wid], ~((u64)killed << (lane * PER)));
                }
            }
        }
        __syncthreads();
        if (sStop) break;
        dLo = sDLo[0];
        dHi = sDHi[0];
    }

    if (tid < NWORD && tid > sStopT) alive[tid] = 0ull;
    __syncthreads();

    // ---------- Phase 5: ranks + emit top-K with NEG padding ----------
    if (tid == 0) {
        int acc = 0;
        #pragma unroll
        for (int w = 0; w < NWORD; w++) { wp[w] = acc; acc += __popcll(alive[w]); }
        wp[NWORD] = acc;
    }
    __syncthreads();
    const int T = wp[NWORD];
    float* o = out + ((size_t)(b * 2 + c)) * Kq * 3;

    const u64 aw = alive[wid];
    #pragma unroll
    for (int r = 0; r < PER; r++) {
        int p = base + r;
        int bit = p & 63;
        u64 lowmask = (bit == 0) ? 0ull : ((1ull << bit) - 1ull);
        int  kr   = wp[p >> 6] + __popcll(aw & lowmask);
        bool kept = (aw >> bit) & 1ull;
        if (kept) {
            if (kr < Kq) {
                o[kr * 3 + 0] = myLo[r];
                o[kr * 3 + 1] = myHi[r];
                o[kr * 3 + 2] = key_to_score((unsigned)(myKey[r] >> 32));
            }
        } else {
            int nr = p - kr;
            if (T < Kq && nr < Kq - T) {
                int slot = T + nr;
                o[slot * 3 + 0] = myLo[r];
                o[slot * 3 + 1] = myHi[r];
                o[slot * 3 + 2] = NEGV;
            }
        }
    }
}

extern "C" void kernel_launch(void* const* d_in, const int* in_sizes, int n_in,
                              void* d_out, int out_size)
{
    const float* logit  = (const float*)d_in[0];   // [16,2048,3]
    const float* reg    = (const float*)d_in[1];   // [16,2048,6]
    const float* prop   = (const float*)d_in[2];   // [16,2048,2]
    const int*   ishape = (const int*)d_in[3];     // scalar
    float* out = (float*)d_out;                    // [16,2,100,3]

    cudaFuncSetAttribute(roiheads_kernel,
                         cudaFuncAttributeMaxDynamicSharedMemorySize, SMEM_DYN);
    roiheads_kernel<<<Bq * (Cq - 1), THREADS, SMEM_DYN>>>(logit, reg, prop, ishape, out);
}